// round 3
// baseline (speedup 1.0000x reference)
#include <cuda_runtime.h>
#include <math.h>
#include <stdint.h>

#define G   128
#define NT  256
#define TT  4800

// shared-memory float offsets
#define OFF_WI   0
#define OFF_WIB  452
#define OFF_G1I  456
#define OFF_G1H  6600
#define OFF_G1B  12744
#define OFF_G2I  12760
#define OFF_G2H  19288
#define OFF_G2B  25432
#define OFF_F1W  25448
#define OFF_F1B  27624
#define OFF_F2W  27628
#define OFF_F2B  29804
#define OFF_F3W  29808
#define OFF_F3B  31856
#define OFF_ACTA 31860
#define OFF_ACTH 34036
#define OFF_STAG 36084
#define OFF_SAMP 36180
#define SMEMF    36184
#define SMEM_BYTES (SMEMF * 4)

__device__ float g_x[512*4], g_x2[512*4], g_x3[512*4], g_y1[512*4], g_y2[512*4];
__device__ float g_h1[2][512*4], g_h2[2][512*4];
__device__ unsigned long long g_cand[G*4];
__device__ unsigned int g_flags[G*32];   // padded: one 128B line per CTA

__device__ __forceinline__ unsigned int ld_acq(const unsigned int* p){
    unsigned int v;
    asm volatile("ld.acquire.gpu.global.b32 %0, [%1];" : "=r"(v) : "l"(p) : "memory");
    return v;
}
__device__ __forceinline__ void st_rel(unsigned int* p, unsigned int v){
    asm volatile("st.release.gpu.global.b32 [%0], %1;" :: "l"(p), "r"(v) : "memory");
}

__device__ __forceinline__ void gbar(int bx, unsigned int& ep){
    __syncthreads();
    ep++;
    if (threadIdx.x == 0) st_rel(&g_flags[bx*32], ep);
    if (threadIdx.x < G){
        const unsigned int* f = &g_flags[threadIdx.x*32];
        while ((int)(ld_acq(f) - ep) < 0) {}
    }
    __syncthreads();
}

__device__ __forceinline__ void load_act512(float* sm, int off, const float* gsrc){
    float4* d = (float4*)(sm + off);
    const float4* s = (const float4*)gsrc;
    for (int i = threadIdx.x; i < 512; i += NT) d[i] = __ldcg(s + i);
}
__device__ __forceinline__ void load_aux32(float* sm, const float* aux, int t, int c){
    int tid = threadIdx.x;
    if (tid < 128){
        int j = tid >> 2, b = tid & 3;
        sm[OFF_ACTA + (512 + j)*4 + b] = aux[(b*TT + t)*128 + c*32 + j];
    }
}

// FC-style stage: 8 warps = 4 neurons x 2 K-halves, batch-4 in regs.
__device__ __forceinline__ void fc_stage(float* sm, int offW, int offB, int K, int n0,
                                         float* out_g, bool dorelu){
    const int tid = threadIdx.x, w = tid >> 5, lane = tid & 31;
    const int n = w >> 1, kh = w & 1;
    const int Kh = (K + 1) >> 1;
    const int kb = kh * Kh;
    const int ke = (kb + Kh < K) ? (kb + Kh) : K;
    const float4* A = (const float4*)(sm + OFF_ACTA);
    const float*  W = sm + offW + n * K;
    float a0=0.f, a1=0.f, a2=0.f, a3=0.f;
    #pragma unroll 2
    for (int k = kb + lane; k < ke; k += 32){
        float4 a = A[k]; float wv = W[k];
        a0 = fmaf(wv, a.x, a0); a1 = fmaf(wv, a.y, a1);
        a2 = fmaf(wv, a.z, a2); a3 = fmaf(wv, a.w, a3);
    }
    #pragma unroll
    for (int o = 16; o; o >>= 1){
        a0 += __shfl_xor_sync(0xffffffffu, a0, o);
        a1 += __shfl_xor_sync(0xffffffffu, a1, o);
        a2 += __shfl_xor_sync(0xffffffffu, a2, o);
        a3 += __shfl_xor_sync(0xffffffffu, a3, o);
    }
    if (!lane){
        float* S = sm + OFF_STAG + (n*2 + kh)*4;
        S[0]=a0; S[1]=a1; S[2]=a2; S[3]=a3;
    }
    __syncthreads();
    if (tid < 16){
        int nn = tid >> 2, b = tid & 3;
        float v = sm[OFF_STAG + nn*8 + b] + sm[OFF_STAG + nn*8 + 4 + b] + sm[offB + nn];
        if (dorelu) v = fmaxf(v, 0.f);
        out_g[(n0 + nn)*4 + b] = v;
    }
}

// GRU stage: 8 warps = 4 neurons x {input-side, hidden-side}; 3 gates at once.
__device__ __forceinline__ void gru_stage(float* sm, int offI, int offH, int offB, int Kin,
                                          int n0, float* hnew_g, float* xnew_g){
    const int tid = threadIdx.x, w = tid >> 5, lane = tid & 31;
    const int n = w >> 1, half = w & 1;
    const float4* A = (const float4*)(sm + (half ? OFF_ACTH : OFF_ACTA));
    const int K = half ? 512 : Kin;
    const float* W = sm + (half ? offH : offI) + n * 3 * K;
    float acc[3][4];
    #pragma unroll
    for (int g = 0; g < 3; g++){ acc[g][0]=0.f; acc[g][1]=0.f; acc[g][2]=0.f; acc[g][3]=0.f; }
    #pragma unroll 2
    for (int k = lane; k < K; k += 32){
        float4 a = A[k];
        #pragma unroll
        for (int g = 0; g < 3; g++){
            float wv = W[g*K + k];
            acc[g][0] = fmaf(wv, a.x, acc[g][0]);
            acc[g][1] = fmaf(wv, a.y, acc[g][1]);
            acc[g][2] = fmaf(wv, a.z, acc[g][2]);
            acc[g][3] = fmaf(wv, a.w, acc[g][3]);
        }
    }
    #pragma unroll
    for (int o = 16; o; o >>= 1)
        #pragma unroll
        for (int g = 0; g < 3; g++)
            #pragma unroll
            for (int b = 0; b < 4; b++)
                acc[g][b] += __shfl_xor_sync(0xffffffffu, acc[g][b], o);
    if (!lane)
        #pragma unroll
        for (int g = 0; g < 3; g++)
            #pragma unroll
            for (int b = 0; b < 4; b++)
                sm[OFF_STAG + (n*24 + half*12 + g*4) + b] = acc[g][b];
    __syncthreads();
    if (tid < 16){
        int nn = tid >> 2, b = tid & 3;
        const float* S = sm + OFF_STAG + nn*24;
        float ir = S[b],      iz = S[4 + b],  in_ = S[8 + b];
        float hr = S[12 + b], hz = S[16 + b], hn  = S[20 + b];
        const float* B = sm + offB + nn*4;
        float r  = 1.f / (1.f + expf(-(ir + hr + B[0])));
        float z  = 1.f / (1.f + expf(-(iz + hz + B[1])));
        float nv = tanhf(in_ + B[2] + r * (hn + B[3]));
        float hold = sm[OFF_ACTH + (n0 + nn)*4 + b];
        float hv = (1.f - z) * nv + z * hold;
        hnew_g[(n0 + nn)*4 + b] = hv;
        xnew_g[(n0 + nn)*4 + b] = sm[OFF_ACTA + (n0 + nn)*4 + b] + hv;
    }
}

// fc3 + logits write + per-CTA argmax candidate
__device__ __forceinline__ void fc3_stage(float* sm, int n0, int bx, float* outL, int t){
    const int tid = threadIdx.x, w = tid >> 5, lane = tid & 31;
    const int n = w >> 1, kh = w & 1;
    const int kb = kh * 256;
    const float4* A = (const float4*)(sm + OFF_ACTA);
    const float*  W = sm + OFF_F3W + n * 512;
    float a0=0.f, a1=0.f, a2=0.f, a3=0.f;
    #pragma unroll 2
    for (int k = kb + lane; k < kb + 256; k += 32){
        float4 a = A[k]; float wv = W[k];
        a0 = fmaf(wv, a.x, a0); a1 = fmaf(wv, a.y, a1);
        a2 = fmaf(wv, a.z, a2); a3 = fmaf(wv, a.w, a3);
    }
    #pragma unroll
    for (int o = 16; o; o >>= 1){
        a0 += __shfl_xor_sync(0xffffffffu, a0, o);
        a1 += __shfl_xor_sync(0xffffffffu, a1, o);
        a2 += __shfl_xor_sync(0xffffffffu, a2, o);
        a3 += __shfl_xor_sync(0xffffffffu, a3, o);
    }
    if (!lane){
        float* S = sm + OFF_STAG + (n*2 + kh)*4;
        S[0]=a0; S[1]=a1; S[2]=a2; S[3]=a3;
    }
    __syncthreads();
    if (tid < 16){
        int nn = tid >> 2, b = tid & 3;
        float v = sm[OFF_STAG + nn*8 + b] + sm[OFF_STAG + nn*8 + 4 + b] + sm[OFF_F3B + nn];
        outL[(b*TT + t)*512 + n0 + nn] = v;
        unsigned u = __float_as_uint(v);
        u = (u & 0x80000000u) ? ~u : (u | 0x80000000u);
        unsigned long long key = ((unsigned long long)u << 32) | (unsigned)(511 - (n0 + nn));
        #pragma unroll
        for (int o = 4; o <= 8; o <<= 1){
            unsigned long long kk = __shfl_xor_sync(0xffffu, key, o);
            key = kk > key ? kk : key;
        }
        if (tid < 4) g_cand[bx*4 + tid] = key;
    }
}

extern "C" __global__ void __launch_bounds__(NT, 1) wavernn_kernel(
    const float* __restrict__ mel,   const float* __restrict__ aux,
    const float* __restrict__ WI,    const float* __restrict__ bI,
    const float* __restrict__ g1wih, const float* __restrict__ g1whh,
    const float* __restrict__ g1bih, const float* __restrict__ g1bhh,
    const float* __restrict__ g2wih, const float* __restrict__ g2whh,
    const float* __restrict__ g2bih, const float* __restrict__ g2bhh,
    const float* __restrict__ f1w,   const float* __restrict__ f1b,
    const float* __restrict__ f2w,   const float* __restrict__ f2b,
    const float* __restrict__ f3w,   const float* __restrict__ f3b,
    float* __restrict__ out)
{
    extern __shared__ float sm[];
    const int tid = threadIdx.x, bx = blockIdx.x, n0 = bx * 4;
    unsigned int ep = ld_acq(&g_flags[bx*32]);   // monotonic epoch base across replays

    // ---- one-time weight load into SMEM ----
    for (int i = tid; i < 452; i += NT){ int j=i/113, k=i-j*113; sm[OFF_WI+i] = WI[(n0+j)*113 + k]; }
    if (tid < 4) sm[OFF_WIB + tid] = bI[n0 + tid];
    for (int i = tid; i < 6144; i += NT){
        int j=i/1536, r=i-j*1536, g=r>>9, k=r&511;
        sm[OFF_G1I+i] = g1wih[(g*512 + n0 + j)*512 + k];
        sm[OFF_G1H+i] = g1whh[(g*512 + n0 + j)*512 + k];
        sm[OFF_G2H+i] = g2whh[(g*512 + n0 + j)*512 + k];
    }
    for (int i = tid; i < 6528; i += NT){
        int j=i/1632, r=i-j*1632, g=r/544, k=r-g*544;
        sm[OFF_G2I+i] = g2wih[(g*512 + n0 + j)*544 + k];
    }
    if (tid < 16){
        int nn = tid >> 2, c = tid & 3, n = n0 + nn;
        float v1, v2;
        if      (c == 0){ v1 = g1bih[n]      + g1bhh[n];      v2 = g2bih[n]      + g2bhh[n]; }
        else if (c == 1){ v1 = g1bih[512+n]  + g1bhh[512+n];  v2 = g2bih[512+n]  + g2bhh[512+n]; }
        else if (c == 2){ v1 = g1bih[1024+n];                 v2 = g2bih[1024+n]; }
        else            { v1 = g1bhh[1024+n];                 v2 = g2bhh[1024+n]; }
        sm[OFF_G1B + tid] = v1; sm[OFF_G2B + tid] = v2;
    }
    for (int i = tid; i < 2176; i += NT){
        int j=i/544, k=i-j*544;
        sm[OFF_F1W+i] = f1w[(n0+j)*544 + k];
        sm[OFF_F2W+i] = f2w[(n0+j)*544 + k];
    }
    for (int i = tid; i < 2048; i += NT){
        int j=i>>9, k=i&511;
        sm[OFF_F3W+i] = f3w[(n0+j)*512 + k];
    }
    if (tid < 4){
        sm[OFF_F1B+tid] = f1b[n0+tid]; sm[OFF_F2B+tid] = f2b[n0+tid];
        sm[OFF_F3B+tid] = f3b[n0+tid]; sm[OFF_SAMP+tid] = 0.f;
    }
    if (tid < 16){
        int nn = tid >> 2, b = tid & 3;
        g_h1[0][(n0+nn)*4 + b] = 0.f;
        g_h2[0][(n0+nn)*4 + b] = 0.f;
    }
    gbar(bx, ep);

    float* outS = out;            // samples [4][4800]
    float* outL = out + 4*TT;     // logits  [4][4800][512]

    for (int t = 0; t < TT; t++){
        const int par = t & 1;
        // S1: input layer, x = W_I @ [sample, mel, aux0] + b_I
        if (tid < 4) sm[OFF_ACTA + tid] = sm[OFF_SAMP + tid];
        for (int i = tid; i < 320; i += NT){
            int j = i >> 2, b = i & 3;
            sm[OFF_ACTA + (1+j)*4 + b] = mel[(b*TT + t)*80 + j];
        }
        if (tid < 128){
            int j = tid >> 2, b = tid & 3;
            sm[OFF_ACTA + (81+j)*4 + b] = aux[(b*TT + t)*128 + j];
        }
        __syncthreads();
        fc_stage(sm, OFF_WI, OFF_WIB, 113, n0, g_x, false);
        gbar(bx, ep);

        // S2: GRU1
        load_act512(sm, OFF_ACTA, g_x);
        load_act512(sm, OFF_ACTH, g_h1[par]);
        __syncthreads();
        gru_stage(sm, OFF_G1I, OFF_G1H, OFF_G1B, 512, n0, g_h1[par^1], g_x2);
        gbar(bx, ep);

        // S3: GRU2 (input = [x2, aux1])
        load_act512(sm, OFF_ACTA, g_x2);
        load_aux32(sm, aux, t, 1);
        load_act512(sm, OFF_ACTH, g_h2[par]);
        __syncthreads();
        gru_stage(sm, OFF_G2I, OFF_G2H, OFF_G2B, 544, n0, g_h2[par^1], g_x3);
        gbar(bx, ep);

        // S4: fc1 (relu)
        load_act512(sm, OFF_ACTA, g_x3);
        load_aux32(sm, aux, t, 2);
        __syncthreads();
        fc_stage(sm, OFF_F1W, OFF_F1B, 544, n0, g_y1, true);
        gbar(bx, ep);

        // S5: fc2 (relu)
        load_act512(sm, OFF_ACTA, g_y1);
        load_aux32(sm, aux, t, 3);
        __syncthreads();
        fc_stage(sm, OFF_F2W, OFF_F2B, 544, n0, g_y2, true);
        gbar(bx, ep);

        // S6: fc3 + logits + local argmax candidate
        load_act512(sm, OFF_ACTA, g_y2);
        __syncthreads();
        fc3_stage(sm, n0, bx, outL, t);
        gbar(bx, ep);

        // argmax all-reduce (every CTA, no extra barrier): warp w = batch w
        if (tid < 128){
            int w = tid >> 5, lane = tid & 31;
            unsigned long long c = 0ull;
            #pragma unroll
            for (int j = 0; j < 4; j++){
                unsigned long long v = __ldcg(&g_cand[(lane + 32*j)*4 + w]);
                c = v > c ? v : c;
            }
            #pragma unroll
            for (int o = 16; o; o >>= 1){
                unsigned long long v = __shfl_xor_sync(0xffffffffu, c, o);
                c = v > c ? v : c;
            }
            if (lane == 0){
                int idx = 511 - (int)(c & 0xffffffffull);   // recovered neuron index
                float s = 2.f * (float)idx / 511.f - 1.f;
                sm[OFF_SAMP + w] = s;
                if (bx == 0) outS[w*TT + t] = s;
            }
        }
        __syncthreads();
    }
}

extern "C" void kernel_launch(void* const* d_in, const int* in_sizes, int n_in,
                              void* d_out, int out_size){
    (void)in_sizes; (void)n_in; (void)out_size;
    cudaFuncSetAttribute(wavernn_kernel, cudaFuncAttributeMaxDynamicSharedMemorySize, SMEM_BYTES);
    wavernn_kernel<<<G, NT, SMEM_BYTES>>>(
        (const float*)d_in[0],  (const float*)d_in[1],  (const float*)d_in[2],
        (const float*)d_in[3],  (const float*)d_in[4],  (const float*)d_in[5],
        (const float*)d_in[6],  (const float*)d_in[7],  (const float*)d_in[8],
        (const float*)d_in[9],  (const float*)d_in[10], (const float*)d_in[11],
        (const float*)d_in[12], (const float*)d_in[13], (const float*)d_in[14],
        (const float*)d_in[15], (const float*)d_in[16], (const float*)d_in[17],
        (float*)d_out);
}

// round 4
// speedup vs baseline: 1.0005x; 1.0005x over previous
#include <cuda_runtime.h>
#include <math.h>
#include <stdint.h>

#define G   128
#define NT  256
#define TT  4800

// shared-memory float offsets
#define OFF_WI   0
#define OFF_WIB  452
#define OFF_G1I  456
#define OFF_G1H  6600
#define OFF_G1B  12744
#define OFF_G2I  12760
#define OFF_G2H  19288
#define OFF_G2B  25432
#define OFF_F1W  25448
#define OFF_F1B  27624
#define OFF_F2W  27628
#define OFF_F2B  29804
#define OFF_F3W  29808
#define OFF_F3B  31856
#define OFF_ACTA 31860
#define OFF_ACTH 34036
#define OFF_STAG 36084
#define OFF_SAMP 36180
#define SMEMF    36184
#define SMEM_BYTES (SMEMF * 4)

__device__ float g_x[512*4], g_x2[512*4], g_x3[512*4], g_y1[512*4], g_y2[512*4];
__device__ float g_h1[2][512*4], g_h2[2][512*4];
__device__ unsigned long long g_cand[G*4];
__device__ unsigned int g_flags[G*32];   // padded: one 128B line per CTA

__device__ __forceinline__ unsigned int ld_acq(const unsigned int* p){
    unsigned int v;
    asm volatile("ld.acquire.gpu.global.b32 %0, [%1];" : "=r"(v) : "l"(p) : "memory");
    return v;
}
__device__ __forceinline__ void st_rel(unsigned int* p, unsigned int v){
    asm volatile("st.release.gpu.global.b32 [%0], %1;" :: "l"(p), "r"(v) : "memory");
}

__device__ __forceinline__ void gbar(int bx, unsigned int& ep){
    __syncthreads();
    ep++;
    if (threadIdx.x == 0) st_rel(&g_flags[bx*32], ep);
    if (threadIdx.x < G){
        const unsigned int* f = &g_flags[threadIdx.x*32];
        while ((int)(ld_acq(f) - ep) < 0) {}
    }
    __syncthreads();
}

__device__ __forceinline__ void load_act512(float* sm, int off, const float* gsrc){
    float4* d = (float4*)(sm + off);
    const float4* s = (const float4*)gsrc;
    for (int i = threadIdx.x; i < 512; i += NT) d[i] = __ldcg(s + i);
}
__device__ __forceinline__ void load_aux32(float* sm, const float* aux, int t, int c){
    int tid = threadIdx.x;
    if (tid < 128){
        int j = tid >> 2, b = tid & 3;
        sm[OFF_ACTA + (512 + j)*4 + b] = aux[(b*TT + t)*128 + c*32 + j];
    }
}

// FC-style stage: 8 warps = 4 neurons x 2 K-halves, batch-4 in regs.
__device__ __forceinline__ void fc_stage(float* sm, int offW, int offB, int K, int n0,
                                         float* out_g, bool dorelu){
    const int tid = threadIdx.x, w = tid >> 5, lane = tid & 31;
    const int n = w >> 1, kh = w & 1;
    const int Kh = (K + 1) >> 1;
    const int kb = kh * Kh;
    const int ke = (kb + Kh < K) ? (kb + Kh) : K;
    const float4* A = (const float4*)(sm + OFF_ACTA);
    const float*  W = sm + offW + n * K;
    float a0=0.f, a1=0.f, a2=0.f, a3=0.f;
    #pragma unroll 2
    for (int k = kb + lane; k < ke; k += 32){
        float4 a = A[k]; float wv = W[k];
        a0 = fmaf(wv, a.x, a0); a1 = fmaf(wv, a.y, a1);
        a2 = fmaf(wv, a.z, a2); a3 = fmaf(wv, a.w, a3);
    }
    #pragma unroll
    for (int o = 16; o; o >>= 1){
        a0 += __shfl_xor_sync(0xffffffffu, a0, o);
        a1 += __shfl_xor_sync(0xffffffffu, a1, o);
        a2 += __shfl_xor_sync(0xffffffffu, a2, o);
        a3 += __shfl_xor_sync(0xffffffffu, a3, o);
    }
    if (!lane){
        float* S = sm + OFF_STAG + (n*2 + kh)*4;
        S[0]=a0; S[1]=a1; S[2]=a2; S[3]=a3;
    }
    __syncthreads();
    if (tid < 16){
        int nn = tid >> 2, b = tid & 3;
        float v = sm[OFF_STAG + nn*8 + b] + sm[OFF_STAG + nn*8 + 4 + b] + sm[offB + nn];
        if (dorelu) v = fmaxf(v, 0.f);
        out_g[(n0 + nn)*4 + b] = v;
    }
}

// GRU stage: 8 warps = 4 neurons x {input-side, hidden-side}; 3 gates at once.
__device__ __forceinline__ void gru_stage(float* sm, int offI, int offH, int offB, int Kin,
                                          int n0, float* hnew_g, float* xnew_g){
    const int tid = threadIdx.x, w = tid >> 5, lane = tid & 31;
    const int n = w >> 1, half = w & 1;
    const float4* A = (const float4*)(sm + (half ? OFF_ACTH : OFF_ACTA));
    const int K = half ? 512 : Kin;
    const float* W = sm + (half ? offH : offI) + n * 3 * K;
    float acc[3][4];
    #pragma unroll
    for (int g = 0; g < 3; g++){ acc[g][0]=0.f; acc[g][1]=0.f; acc[g][2]=0.f; acc[g][3]=0.f; }
    #pragma unroll 2
    for (int k = lane; k < K; k += 32){
        float4 a = A[k];
        #pragma unroll
        for (int g = 0; g < 3; g++){
            float wv = W[g*K + k];
            acc[g][0] = fmaf(wv, a.x, acc[g][0]);
            acc[g][1] = fmaf(wv, a.y, acc[g][1]);
            acc[g][2] = fmaf(wv, a.z, acc[g][2]);
            acc[g][3] = fmaf(wv, a.w, acc[g][3]);
        }
    }
    #pragma unroll
    for (int o = 16; o; o >>= 1)
        #pragma unroll
        for (int g = 0; g < 3; g++)
            #pragma unroll
            for (int b = 0; b < 4; b++)
                acc[g][b] += __shfl_xor_sync(0xffffffffu, acc[g][b], o);
    if (!lane)
        #pragma unroll
        for (int g = 0; g < 3; g++)
            #pragma unroll
            for (int b = 0; b < 4; b++)
                sm[OFF_STAG + (n*24 + half*12 + g*4) + b] = acc[g][b];
    __syncthreads();
    if (tid < 16){
        int nn = tid >> 2, b = tid & 3;
        const float* S = sm + OFF_STAG + nn*24;
        float ir = S[b],      iz = S[4 + b],  in_ = S[8 + b];
        float hr = S[12 + b], hz = S[16 + b], hn  = S[20 + b];
        const float* B = sm + offB + nn*4;
        float r  = 1.f / (1.f + expf(-(ir + hr + B[0])));
        float z  = 1.f / (1.f + expf(-(iz + hz + B[1])));
        float nv = tanhf(in_ + B[2] + r * (hn + B[3]));
        float hold = sm[OFF_ACTH + (n0 + nn)*4 + b];
        float hv = (1.f - z) * nv + z * hold;
        hnew_g[(n0 + nn)*4 + b] = hv;
        xnew_g[(n0 + nn)*4 + b] = sm[OFF_ACTA + (n0 + nn)*4 + b] + hv;
    }
}

// fc3 + logits write + per-CTA argmax candidate
__device__ __forceinline__ void fc3_stage(float* sm, int n0, int bx, float* outL, int t){
    const int tid = threadIdx.x, w = tid >> 5, lane = tid & 31;
    const int n = w >> 1, kh = w & 1;
    const int kb = kh * 256;
    const float4* A = (const float4*)(sm + OFF_ACTA);
    const float*  W = sm + OFF_F3W + n * 512;
    float a0=0.f, a1=0.f, a2=0.f, a3=0.f;
    #pragma unroll 2
    for (int k = kb + lane; k < kb + 256; k += 32){
        float4 a = A[k]; float wv = W[k];
        a0 = fmaf(wv, a.x, a0); a1 = fmaf(wv, a.y, a1);
        a2 = fmaf(wv, a.z, a2); a3 = fmaf(wv, a.w, a3);
    }
    #pragma unroll
    for (int o = 16; o; o >>= 1){
        a0 += __shfl_xor_sync(0xffffffffu, a0, o);
        a1 += __shfl_xor_sync(0xffffffffu, a1, o);
        a2 += __shfl_xor_sync(0xffffffffu, a2, o);
        a3 += __shfl_xor_sync(0xffffffffu, a3, o);
    }
    if (!lane){
        float* S = sm + OFF_STAG + (n*2 + kh)*4;
        S[0]=a0; S[1]=a1; S[2]=a2; S[3]=a3;
    }
    __syncthreads();
    if (tid < 16){
        int nn = tid >> 2, b = tid & 3;
        float v = sm[OFF_STAG + nn*8 + b] + sm[OFF_STAG + nn*8 + 4 + b] + sm[OFF_F3B + nn];
        outL[(b*TT + t)*512 + n0 + nn] = v;
        unsigned u = __float_as_uint(v);
        u = (u & 0x80000000u) ? ~u : (u | 0x80000000u);
        unsigned long long key = ((unsigned long long)u << 32) | (unsigned)(511 - (n0 + nn));
        #pragma unroll
        for (int o = 4; o <= 8; o <<= 1){
            unsigned long long kk = __shfl_xor_sync(0xffffu, key, o);
            key = kk > key ? kk : key;
        }
        if (tid < 4) g_cand[bx*4 + tid] = key;
    }
}

extern "C" __global__ void __launch_bounds__(NT, 1) wavernn_kernel(
    const float* __restrict__ mel,   const float* __restrict__ aux,
    const float* __restrict__ WI,    const float* __restrict__ bI,
    const float* __restrict__ g1wih, const float* __restrict__ g1whh,
    const float* __restrict__ g1bih, const float* __restrict__ g1bhh,
    const float* __restrict__ g2wih, const float* __restrict__ g2whh,
    const float* __restrict__ g2bih, const float* __restrict__ g2bhh,
    const float* __restrict__ f1w,   const float* __restrict__ f1b,
    const float* __restrict__ f2w,   const float* __restrict__ f2b,
    const float* __restrict__ f3w,   const float* __restrict__ f3b,
    float* __restrict__ out)
{
    extern __shared__ float sm[];
    const int tid = threadIdx.x, bx = blockIdx.x, n0 = bx * 4;
    unsigned int ep = ld_acq(&g_flags[bx*32]);   // monotonic epoch base across replays

    // ---- one-time weight load into SMEM ----
    for (int i = tid; i < 452; i += NT){ int j=i/113, k=i-j*113; sm[OFF_WI+i] = WI[(n0+j)*113 + k]; }
    if (tid < 4) sm[OFF_WIB + tid] = bI[n0 + tid];
    for (int i = tid; i < 6144; i += NT){
        int j=i/1536, r=i-j*1536, g=r>>9, k=r&511;
        sm[OFF_G1I+i] = g1wih[(g*512 + n0 + j)*512 + k];
        sm[OFF_G1H+i] = g1whh[(g*512 + n0 + j)*512 + k];
        sm[OFF_G2H+i] = g2whh[(g*512 + n0 + j)*512 + k];
    }
    for (int i = tid; i < 6528; i += NT){
        int j=i/1632, r=i-j*1632, g=r/544, k=r-g*544;
        sm[OFF_G2I+i] = g2wih[(g*512 + n0 + j)*544 + k];
    }
    if (tid < 16){
        int nn = tid >> 2, c = tid & 3, n = n0 + nn;
        float v1, v2;
        if      (c == 0){ v1 = g1bih[n]      + g1bhh[n];      v2 = g2bih[n]      + g2bhh[n]; }
        else if (c == 1){ v1 = g1bih[512+n]  + g1bhh[512+n];  v2 = g2bih[512+n]  + g2bhh[512+n]; }
        else if (c == 2){ v1 = g1bih[1024+n];                 v2 = g2bih[1024+n]; }
        else            { v1 = g1bhh[1024+n];                 v2 = g2bhh[1024+n]; }
        sm[OFF_G1B + tid] = v1; sm[OFF_G2B + tid] = v2;
    }
    for (int i = tid; i < 2176; i += NT){
        int j=i/544, k=i-j*544;
        sm[OFF_F1W+i] = f1w[(n0+j)*544 + k];
        sm[OFF_F2W+i] = f2w[(n0+j)*544 + k];
    }
    for (int i = tid; i < 2048; i += NT){
        int j=i>>9, k=i&511;
        sm[OFF_F3W+i] = f3w[(n0+j)*512 + k];
    }
    if (tid < 4){
        sm[OFF_F1B+tid] = f1b[n0+tid]; sm[OFF_F2B+tid] = f2b[n0+tid];
        sm[OFF_F3B+tid] = f3b[n0+tid]; sm[OFF_SAMP+tid] = 0.f;
    }
    if (tid < 16){
        int nn = tid >> 2, b = tid & 3;
        g_h1[0][(n0+nn)*4 + b] = 0.f;
        g_h2[0][(n0+nn)*4 + b] = 0.f;
    }
    gbar(bx, ep);

    float* outS = out;            // samples [4][4800]
    float* outL = out + 4*TT;     // logits  [4][4800][512]

    for (int t = 0; t < TT; t++){
        const int par = t & 1;
        // S1: input layer, x = W_I @ [sample, mel, aux0] + b_I
        if (tid < 4) sm[OFF_ACTA + tid] = sm[OFF_SAMP + tid];
        for (int i = tid; i < 320; i += NT){
            int j = i >> 2, b = i & 3;
            sm[OFF_ACTA + (1+j)*4 + b] = mel[(b*TT + t)*80 + j];
        }
        if (tid < 128){
            int j = tid >> 2, b = tid & 3;
            sm[OFF_ACTA + (81+j)*4 + b] = aux[(b*TT + t)*128 + j];
        }
        __syncthreads();
        fc_stage(sm, OFF_WI, OFF_WIB, 113, n0, g_x, false);
        gbar(bx, ep);

        // S2: GRU1
        load_act512(sm, OFF_ACTA, g_x);
        load_act512(sm, OFF_ACTH, g_h1[par]);
        __syncthreads();
        gru_stage(sm, OFF_G1I, OFF_G1H, OFF_G1B, 512, n0, g_h1[par^1], g_x2);
        gbar(bx, ep);

        // S3: GRU2 (input = [x2, aux1])
        load_act512(sm, OFF_ACTA, g_x2);
        load_aux32(sm, aux, t, 1);
        load_act512(sm, OFF_ACTH, g_h2[par]);
        __syncthreads();
        gru_stage(sm, OFF_G2I, OFF_G2H, OFF_G2B, 544, n0, g_h2[par^1], g_x3);
        gbar(bx, ep);

        // S4: fc1 (relu)
        load_act512(sm, OFF_ACTA, g_x3);
        load_aux32(sm, aux, t, 2);
        __syncthreads();
        fc_stage(sm, OFF_F1W, OFF_F1B, 544, n0, g_y1, true);
        gbar(bx, ep);

        // S5: fc2 (relu)
        load_act512(sm, OFF_ACTA, g_y1);
        load_aux32(sm, aux, t, 3);
        __syncthreads();
        fc_stage(sm, OFF_F2W, OFF_F2B, 544, n0, g_y2, true);
        gbar(bx, ep);

        // S6: fc3 + logits + local argmax candidate
        load_act512(sm, OFF_ACTA, g_y2);
        __syncthreads();
        fc3_stage(sm, n0, bx, outL, t);
        gbar(bx, ep);

        // argmax all-reduce (every CTA, no extra barrier): warp w = batch w
        if (tid < 128){
            int w = tid >> 5, lane = tid & 31;
            unsigned long long c = 0ull;
            #pragma unroll
            for (int j = 0; j < 4; j++){
                unsigned long long v = __ldcg(&g_cand[(lane + 32*j)*4 + w]);
                c = v > c ? v : c;
            }
            #pragma unroll
            for (int o = 16; o; o >>= 1){
                unsigned long long v = __shfl_xor_sync(0xffffffffu, c, o);
                c = v > c ? v : c;
            }
            if (lane == 0){
                int idx = 511 - (int)(c & 0xffffffffull);   // recovered neuron index
                float s = 2.f * (float)idx / 511.f - 1.f;
                sm[OFF_SAMP + w] = s;
                if (bx == 0) outS[w*TT + t] = s;
            }
        }
        __syncthreads();
    }
}

extern "C" void kernel_launch(void* const* d_in, const int* in_sizes, int n_in,
                              void* d_out, int out_size){
    (void)in_sizes; (void)n_in; (void)out_size;
    cudaFuncSetAttribute(wavernn_kernel, cudaFuncAttributeMaxDynamicSharedMemorySize, SMEM_BYTES);
    wavernn_kernel<<<G, NT, SMEM_BYTES>>>(
        (const float*)d_in[0],  (const float*)d_in[1],  (const float*)d_in[2],
        (const float*)d_in[3],  (const float*)d_in[4],  (const float*)d_in[5],
        (const float*)d_in[6],  (const float*)d_in[7],  (const float*)d_in[8],
        (const float*)d_in[9],  (const float*)d_in[10], (const float*)d_in[11],
        (const float*)d_in[12], (const float*)d_in[13], (const float*)d_in[14],
        (const float*)d_in[15], (const float*)d_in[16], (const float*)d_in[17],
        (float*)d_out);
}